// round 4
// baseline (speedup 1.0000x reference)
#include <cuda_runtime.h>

// Problem shape (fixed): N=500000, K=81 neighbors, C=4, OUT=8.
#define KNB 81
#define CHUNK 27
#define NCHUNK 3
#define OUTC 8
#define TPB  128
#define PPB  256      // points per block (2 per thread)
#define B3   3        // neighbors per inner batch per point (MLP = 2*B3)
#define CAP  1000000

// Scratch (device global: allocation-free rule)
__device__ float4 g_pts4[CAP];

// ---------- helpers ----------
__device__ __forceinline__ unsigned long long pack2(float a, float b) {
    unsigned long long r;
    asm("mov.b64 %0, {%1, %2};" : "=l"(r) : "f"(a), "f"(b));
    return r;
}
__device__ __forceinline__ void fma2(unsigned long long& acc,
                                     unsigned long long a, unsigned long long b) {
    asm("fma.rn.f32x2 %0, %1, %2, %0;" : "+l"(acc) : "l"(a), "l"(b));
}

// ---------- kernel 1: pad points to float4 with |p|^2 in .w ----------
__global__ void pad_points(const float* __restrict__ pts, int N) {
    int i = blockIdx.x * blockDim.x + threadIdx.x;
    if (i < N) {
        float x = pts[3 * i], y = pts[3 * i + 1], z = pts[3 * i + 2];
        g_pts4[i] = make_float4(x, y, z, x * x + y * y + z * z);
    }
}

// ---------- kernel 2: fused gather + conv, 2 points/thread ----------
__global__ __launch_bounds__(TPB, 6) void conv_main(
    const void* __restrict__ indices_raw,
    const float* __restrict__ dw,       // [81][4]
    const float* __restrict__ weight,   // [4][81][8]
    const float* __restrict__ bias,     // [8]
    float* __restrict__ out,            // [N][8]
    int N)
{
    __shared__ int sIdx[PPB * CHUNK];               // 27648 B
    __shared__ unsigned long long sW[KNB * 16];     // 10368 B: [j][c*4 + lpair]

    const int tid = threadIdx.x;

    // Inline dtype detection (uniform; L2-cached).
    const unsigned long long* iq = (const unsigned long long*)indices_raw;
    bool is64 = (iq[1] < (unsigned long long)N) & (iq[2] < (unsigned long long)N)
              & (iq[3] < (unsigned long long)N) & (iq[4] < (unsigned long long)N);

    // Packed weight table: W[j,c,l] = dw[j,c] * weight[c,j,l], pairs over l.
    for (int e = tid; e < KNB * 16; e += TPB) {
        int j = e >> 4, r = e & 15, c = r >> 2, lp = r & 3;
        float dv = dw[j * 4 + c];
        const float* wp = weight + ((c * KNB + j) * OUTC + 2 * lp);
        sW[e] = pack2(dv * wp[0], dv * wp[1]);
    }

    const int b0 = blockIdx.x * PPB;
    const int npts = min(PPB, N - b0);
    const int nA = b0 + tid;
    const int nB = b0 + TPB + tid;
    const bool actA = (nA < N);
    const bool actB = (nB < N);

    float c0A = 0.f, mxA = 0.f, myA = 0.f, mzA = 0.f;
    float c0B = 0.f, mxB = 0.f, myB = 0.f, mzB = 0.f;
    unsigned long long accA[4], accB[4];
    #pragma unroll
    for (int lp = 0; lp < 4; lp++) {
        unsigned long long bb = pack2(bias[2 * lp], bias[2 * lp + 1]);
        accA[lp] = bb; accB[lp] = bb;
    }

    for (int ch = 0; ch < NCHUNK; ch++) {
        __syncthreads();
        // Stage chunk for all PPB points (coalesced across the row region).
        const int nelem = npts * CHUNK;
        if (is64) {
            const long long* src = (const long long*)indices_raw;
            for (int e = tid; e < nelem; e += TPB) {
                int p = e / CHUNK, j = e - p * CHUNK;
                sIdx[e] = (int)src[(long long)(b0 + p) * KNB + ch * CHUNK + j];
            }
        } else {
            const int* src = (const int*)indices_raw;
            for (int e = tid; e < nelem; e += TPB) {
                int p = e / CHUNK, j = e - p * CHUNK;
                sIdx[e] = src[(long long)(b0 + p) * KNB + ch * CHUNK + j];
            }
        }
        // Zero-fill tail so inactive points gather index 0 (safe).
        for (int e = nelem + tid; e < PPB * CHUNK; e += TPB) sIdx[e] = 0;
        __syncthreads();

        const int* idxA = &sIdx[tid * CHUNK];
        const int* idxB = &sIdx[(TPB + tid) * CHUNK];

        if (ch == 0) {
            float4 sA = g_pts4[idxA[0]];
            float4 sB = g_pts4[idxB[0]];
            c0A = sA.w + 1.0f; mxA = -2.f * sA.x; myA = -2.f * sA.y; mzA = -2.f * sA.z;
            c0B = sB.w + 1.0f; mxB = -2.f * sB.x; myB = -2.f * sB.y; mzB = -2.f * sB.z;
        }

        #pragma unroll
        for (int b = 0; b < CHUNK / B3; b++) {
            float4 pA[B3], pB[B3];
            int iA[B3], iB[B3];
            #pragma unroll
            for (int u = 0; u < B3; u++) { iA[u] = idxA[b * B3 + u]; iB[u] = idxB[b * B3 + u]; }
            #pragma unroll
            for (int u = 0; u < B3; u++) { pA[u] = g_pts4[iA[u]]; pB[u] = g_pts4[iB[u]]; }

            #pragma unroll
            for (int u = 0; u < B3; u++) {
                const int j = ch * CHUNK + b * B3 + u;
                float4 a = pA[u], q = pB[u];

                float dA = a.w + c0A;
                dA = fmaf(mxA, a.x, dA); dA = fmaf(myA, a.y, dA); dA = fmaf(mzA, a.z, dA);
                float dB = q.w + c0B;
                dB = fmaf(mxB, q.x, dB); dB = fmaf(myB, q.y, dB); dB = fmaf(mzB, q.z, dB);

                unsigned long long fA[4], fB[4];
                fA[0] = pack2(a.x, a.x); fA[1] = pack2(a.y, a.y);
                fA[2] = pack2(a.z, a.z); fA[3] = pack2(dA, dA);
                fB[0] = pack2(q.x, q.x); fB[1] = pack2(q.y, q.y);
                fB[2] = pack2(q.z, q.z); fB[3] = pack2(dB, dB);

                const ulonglong2* wrow = (const ulonglong2*)&sW[j * 16];
                #pragma unroll
                for (int c = 0; c < 4; c++) {
                    ulonglong2 wa = wrow[c * 2];      // outputs 0-3 (pair x2)
                    ulonglong2 wb = wrow[c * 2 + 1];  // outputs 4-7
                    fma2(accA[0], fA[c], wa.x);
                    fma2(accA[1], fA[c], wa.y);
                    fma2(accA[2], fA[c], wb.x);
                    fma2(accA[3], fA[c], wb.y);
                    fma2(accB[0], fB[c], wa.x);
                    fma2(accB[1], fB[c], wa.y);
                    fma2(accB[2], fB[c], wb.x);
                    fma2(accB[3], fB[c], wb.y);
                }
            }
        }
    }

    if (actA) {
        float2 o0 = *(float2*)&accA[0], o1 = *(float2*)&accA[1];
        float2 o2 = *(float2*)&accA[2], o3 = *(float2*)&accA[3];
        float4* op = (float4*)(out + (long long)nA * OUTC);
        op[0] = make_float4(o0.x, o0.y, o1.x, o1.y);
        op[1] = make_float4(o2.x, o2.y, o3.x, o3.y);
    }
    if (actB) {
        float2 o0 = *(float2*)&accB[0], o1 = *(float2*)&accB[1];
        float2 o2 = *(float2*)&accB[2], o3 = *(float2*)&accB[3];
        float4* op = (float4*)(out + (long long)nB * OUTC);
        op[0] = make_float4(o0.x, o0.y, o1.x, o1.y);
        op[1] = make_float4(o2.x, o2.y, o3.x, o3.y);
    }
}

// ---------- launcher ----------
extern "C" void kernel_launch(void* const* d_in, const int* in_sizes, int n_in,
                              void* d_out, int out_size) {
    const float* points  = (const float*)d_in[0];   // [N,3]
    const void*  indices = d_in[1];                 // [N,81] int64 or int32
    const float* dw      = (const float*)d_in[2];   // [81,4]
    const float* weight  = (const float*)d_in[3];   // [4,81,8]
    const float* bias    = (const float*)d_in[4];   // [8]
    float* out = (float*)d_out;

    const int N = in_sizes[0] / 3;

    pad_points<<<(N + 255) / 256, 256>>>(points, N);
    conv_main<<<(N + PPB - 1) / PPB, TPB>>>(indices, dw, weight, bias, out, N);
}

// round 5
// speedup vs baseline: 1.2365x; 1.2365x over previous
#include <cuda_runtime.h>

// Problem shape (fixed): N=500000, K=81 neighbors, C=4, OUT=8.
#define KNB 81
#define CHUNK 27
#define NCHUNK 3
#define OUTC 8
#define TPB  128
#define BATCH 9
#define CAP  1000000

// Scratch (device globals: allocation-free rule)
__device__ float4 g_pts4[CAP];
__device__ ulonglong2 g_wtab[KNB * 8];          // staging for constant table
__constant__ ulonglong2 cW[KNB * 8];            // [j][c*2 + half]: packed pairs

// ---------- helpers ----------
__device__ __forceinline__ unsigned long long pack2(float a, float b) {
    unsigned long long r;
    asm("mov.b64 %0, {%1, %2};" : "=l"(r) : "f"(a), "f"(b));
    return r;
}
__device__ __forceinline__ void fma2(unsigned long long& acc,
                                     unsigned long long a, unsigned long long b) {
    asm("fma.rn.f32x2 %0, %1, %2, %0;" : "+l"(acc) : "l"(a), "l"(b));
}

// ---------- kernel 0: build combined weight table ----------
// W[j,c,l] = dw[j,c] * weight[c,j,l]; packed as pairs over l (8 outs = 4 pairs).
__global__ void build_wtab(const float* __restrict__ dw,
                           const float* __restrict__ weight) {
    int e = blockIdx.x * blockDim.x + threadIdx.x;   // over KNB*16 ull elements
    if (e < KNB * 16) {
        int j = e >> 4, r = e & 15, c = r >> 2, lp = r & 3;
        float dv = dw[j * 4 + c];
        const float* wp = weight + ((c * KNB + j) * OUTC + 2 * lp);
        ((unsigned long long*)g_wtab)[e] = pack2(dv * wp[0], dv * wp[1]);
    }
}

// ---------- kernel 1: pad points to float4 with |p|^2 in .w ----------
__global__ void pad_points(const float* __restrict__ pts, int N) {
    int i = blockIdx.x * blockDim.x + threadIdx.x;
    if (i < N) {
        float x = pts[3 * i], y = pts[3 * i + 1], z = pts[3 * i + 2];
        g_pts4[i] = make_float4(x, y, z, x * x + y * y + z * z);
    }
}

// ---------- kernel 2: fused gather + conv (weights via constant port) ----------
__global__ __launch_bounds__(TPB, 7) void conv_main(
    const void* __restrict__ indices_raw,
    const float* __restrict__ bias,     // [8]
    float* __restrict__ out,            // [N][8]
    int N)
{
    __shared__ int sIdx[TPB * CHUNK];               // 13824 B

    const int tid = threadIdx.x;

    // Inline dtype detection (uniform; L2-cached).
    const unsigned long long* iq = (const unsigned long long*)indices_raw;
    bool is64 = (iq[1] < (unsigned long long)N) & (iq[2] < (unsigned long long)N)
              & (iq[3] < (unsigned long long)N) & (iq[4] < (unsigned long long)N);

    const int b0 = blockIdx.x * TPB;
    const int npts = min(TPB, N - b0);
    const int n = b0 + tid;
    const bool active = (n < N);

    float c0 = 0.f, msx = 0.f, msy = 0.f, msz = 0.f;
    unsigned long long acc[4];
    #pragma unroll
    for (int lp = 0; lp < 4; lp++) acc[lp] = pack2(bias[2 * lp], bias[2 * lp + 1]);

    for (int ch = 0; ch < NCHUNK; ch++) {
        __syncthreads();
        const int nelem = npts * CHUNK;
        if (is64) {
            const long long* src = (const long long*)indices_raw;
            for (int e = tid; e < nelem; e += TPB) {
                int p = e / CHUNK, j = e - p * CHUNK;
                sIdx[e] = (int)src[(long long)(b0 + p) * KNB + ch * CHUNK + j];
            }
        } else {
            const int* src = (const int*)indices_raw;
            for (int e = tid; e < nelem; e += TPB) {
                int p = e / CHUNK, j = e - p * CHUNK;
                sIdx[e] = src[(long long)(b0 + p) * KNB + ch * CHUNK + j];
            }
        }
        __syncthreads();

        if (active) {
            const int* myIdx = &sIdx[tid * CHUNK];
            if (ch == 0) {
                float4 s = g_pts4[myIdx[0]];
                c0 = s.w + 1.0f;
                msx = -2.0f * s.x; msy = -2.0f * s.y; msz = -2.0f * s.z;
            }
            #pragma unroll
            for (int b = 0; b < CHUNK / BATCH; b++) {
                int    ibuf[BATCH];
                float4 pbuf[BATCH];
                #pragma unroll
                for (int u = 0; u < BATCH; u++) ibuf[u] = myIdx[b * BATCH + u];
                #pragma unroll
                for (int u = 0; u < BATCH; u++) pbuf[u] = g_pts4[ibuf[u]];

                #pragma unroll
                for (int u = 0; u < BATCH; u++) {
                    const int j = ch * CHUNK + b * BATCH + u;
                    float4 p = pbuf[u];
                    float d = p.w + c0;
                    d = fmaf(msx, p.x, d);
                    d = fmaf(msy, p.y, d);
                    d = fmaf(msz, p.z, d);

                    unsigned long long f[4];
                    f[0] = pack2(p.x, p.x);
                    f[1] = pack2(p.y, p.y);
                    f[2] = pack2(p.z, p.z);
                    f[3] = pack2(d,   d);

                    // Warp-uniform weight rows via the constant port (LDC.128),
                    // off the L1tex/shared pipe entirely.
                    #pragma unroll
                    for (int c = 0; c < 4; c++) {
                        ulonglong2 wa = cW[j * 8 + 2 * c];
                        ulonglong2 wb = cW[j * 8 + 2 * c + 1];
                        fma2(acc[0], f[c], wa.x);
                        fma2(acc[1], f[c], wa.y);
                        fma2(acc[2], f[c], wb.x);
                        fma2(acc[3], f[c], wb.y);
                    }
                }
            }
        }
    }

    if (active) {
        float2 o0 = *(float2*)&acc[0], o1 = *(float2*)&acc[1];
        float2 o2 = *(float2*)&acc[2], o3 = *(float2*)&acc[3];
        float4* op = (float4*)(out + (long long)n * OUTC);
        op[0] = make_float4(o0.x, o0.y, o1.x, o1.y);
        op[1] = make_float4(o2.x, o2.y, o3.x, o3.y);
    }
}

// ---------- launcher ----------
extern "C" void kernel_launch(void* const* d_in, const int* in_sizes, int n_in,
                              void* d_out, int out_size) {
    const float* points  = (const float*)d_in[0];   // [N,3]
    const void*  indices = d_in[1];                 // [N,81] int64 or int32
    const float* dw      = (const float*)d_in[2];   // [81,4]
    const float* weight  = (const float*)d_in[3];   // [4,81,8]
    const float* bias    = (const float*)d_in[4];   // [8]
    float* out = (float*)d_out;

    const int N = in_sizes[0] / 3;

    build_wtab<<<(KNB * 16 + 127) / 128, 128>>>(dw, weight);
    pad_points<<<(N + 255) / 256, 256>>>(points, N);

    // Copy the combined table into the constant bank (D2D, graph-capturable).
    void* csym = nullptr; void* gsym = nullptr;
    cudaGetSymbolAddress(&csym, cW);
    cudaGetSymbolAddress(&gsym, g_wtab);
    cudaMemcpyAsync(csym, gsym, sizeof(ulonglong2) * KNB * 8,
                    cudaMemcpyDeviceToDevice, 0);

    conv_main<<<(N + TPB - 1) / TPB, TPB>>>(indices, bias, out, N);
}